// round 2
// baseline (speedup 1.0000x reference)
#include <cuda_runtime.h>
#include <cuda_bf16.h>

// Problem constants
#define BB 64
#define HH 1024
#define II 512
#define MIN_TAU 1e-3f

#define O_TILE 8   // o-rows per block (one per warp)
#define B_TILE 4   // b-rows per block (looped per warp)
#define OGROUPS (HH / O_TILE)   // 128
#define BGROUPS (BB / B_TILE)   // 16

// Fused ReservoirRNNCell step, 2D-tiled:
//   block = (8 o-rows x 4 b-rows); warp w owns o = og*8+w and loops 4 b's.
// Key restructuring vs R1:
//   - W_hh chunk loaded ONCE per h-chunk into registers, pre-scaled by 1/tau,
//     reused across 4 batch rows  -> W_hh L2 traffic 256MB -> 64MB.
//   - W_ih[o] row reused across the 4-b loop (L1 hit after first b).
//   - h_prev rows shared by all 8 warps of the block via L1.
//   - gumbel (the 268MB mandatory stream) loaded with __ldcs so it does not
//     evict the reused operands from L1.
//   - 4 independent gumbel streams per warp -> 4x DRAM MLP per warp.
// Softmax without max-subtraction is safe: logits bounded by ~18.5
// (Gumbel from u in [1e-8, 1-1e-8]) + O(0.05) from W_hh/tau; fp32 row sums
// stay <= ~1e11. Validated in R1 at rel_err 3.4e-7.
__global__ __launch_bounds__(256, 4) void reservoir_cell_kernel(
    const float* __restrict__ x_t,         // (B, I)
    const float* __restrict__ h_prev,      // (B, H)
    const float* __restrict__ W_ih,        // (H, I)
    const float* __restrict__ b_ih,        // (H,)
    const float* __restrict__ W_hh,        // (H, H)
    const float* __restrict__ temperature, // scalar
    const float* __restrict__ gumbel,      // (B, H, H)
    float* __restrict__ out)               // (B, H)
{
    const int og = blockIdx.x % OGROUPS;
    const int bg = blockIdx.x / OGROUPS;
    const int w    = threadIdx.x >> 5;
    const int lane = threadIdx.x & 31;
    const int o  = og * O_TILE + w;
    const int b0 = bg * B_TILE;

    const float inv_tau = 1.0f / fmaxf(temperature[0], MIN_TAU);

    // ---- input contribution: ic[bi] = dot(x_t[b0+bi,:], W_ih[o,:]) ----
    const float4* __restrict__ wi = reinterpret_cast<const float4*>(W_ih + (size_t)o * II);
    float ic[B_TILE];
#pragma unroll
    for (int bi = 0; bi < B_TILE; ++bi) {
        const float4* __restrict__ xr =
            reinterpret_cast<const float4*>(x_t + (size_t)(b0 + bi) * II);
        float acc = 0.0f;
#pragma unroll
        for (int k = 0; k < 4; ++k) {
            const float4 xv = xr[lane + 32 * k];
            const float4 wv = wi[lane + 32 * k];
            acc = fmaf(xv.x, wv.x, acc);
            acc = fmaf(xv.y, wv.y, acc);
            acc = fmaf(xv.z, wv.z, acc);
            acc = fmaf(xv.w, wv.w, acc);
        }
        ic[bi] = acc;
    }

    // ---- gumbel-softmax weighted mix ----
    const float4* __restrict__ wh =
        reinterpret_cast<const float4*>(W_hh + (size_t)o * HH);
    const float4* __restrict__ gr[B_TILE];
    const float4* __restrict__ hr[B_TILE];
#pragma unroll
    for (int bi = 0; bi < B_TILE; ++bi) {
        gr[bi] = reinterpret_cast<const float4*>(
            gumbel + ((size_t)(b0 + bi) * HH + o) * HH);
        hr[bi] = reinterpret_cast<const float4*>(h_prev + (size_t)(b0 + bi) * HH);
    }

    float s[B_TILE], t[B_TILE];
#pragma unroll
    for (int bi = 0; bi < B_TILE; ++bi) { s[bi] = 0.0f; t[bi] = 0.0f; }

#pragma unroll 4
    for (int k = 0; k < 8; ++k) {
        const int idx = lane + 32 * k;
        // W_hh chunk: loaded once, scaled once, reused for 4 batch rows.
        const float4 wv = wh[idx];
        float4 lw;
        lw.x = wv.x * inv_tau;
        lw.y = wv.y * inv_tau;
        lw.z = wv.z * inv_tau;
        lw.w = wv.w * inv_tau;
#pragma unroll
        for (int bi = 0; bi < B_TILE; ++bi) {
            const float4 g = __ldcs(&gr[bi][idx]);  // streaming: don't pollute L1
            const float4 h = hr[bi][idx];
            float e;
            e = __expf(lw.x + g.x); s[bi] += e; t[bi] = fmaf(e, h.x, t[bi]);
            e = __expf(lw.y + g.y); s[bi] += e; t[bi] = fmaf(e, h.y, t[bi]);
            e = __expf(lw.z + g.z); s[bi] += e; t[bi] = fmaf(e, h.z, t[bi]);
            e = __expf(lw.w + g.w); s[bi] += e; t[bi] = fmaf(e, h.w, t[bi]);
        }
    }

    // ---- warp reductions + epilogue ----
    const float bias = b_ih[o];
#pragma unroll
    for (int bi = 0; bi < B_TILE; ++bi) {
        float sv = s[bi], tv = t[bi], iv = ic[bi];
#pragma unroll
        for (int off = 16; off > 0; off >>= 1) {
            sv += __shfl_xor_sync(0xffffffffu, sv, off);
            tv += __shfl_xor_sync(0xffffffffu, tv, off);
            iv += __shfl_xor_sync(0xffffffffu, iv, off);
        }
        if (lane == 0) {
            out[(size_t)(b0 + bi) * HH + o] = tanhf(iv + bias + tv / sv);
        }
    }
}

extern "C" void kernel_launch(void* const* d_in, const int* in_sizes, int n_in,
                              void* d_out, int out_size) {
    // metadata order: x_t, h_prev, W_ih, b_ih, W_hh, temperature, gumbel_noise
    const float* x_t    = (const float*)d_in[0];
    const float* h_prev = (const float*)d_in[1];
    const float* W_ih   = (const float*)d_in[2];
    const float* b_ih   = (const float*)d_in[3];
    const float* W_hh   = (const float*)d_in[4];
    const float* temp   = (const float*)d_in[5];
    const float* gum    = (const float*)d_in[6];
    float* out = (float*)d_out;

    dim3 grid(OGROUPS * BGROUPS);  // 128 * 16 = 2048 blocks
    dim3 block(O_TILE * 32);       // 256 threads, 8 warps
    reservoir_cell_kernel<<<grid, block>>>(x_t, h_prev, W_ih, b_ih, W_hh, temp, gum, out);
}

// round 3
// speedup vs baseline: 1.0690x; 1.0690x over previous
#include <cuda_runtime.h>
#include <cstdint>

// Problem constants
#define BB 64
#define HH 1024
#define II 512
#define MIN_TAU 1e-3f
#define LOG2E 1.4426950408889634f

// Tiling
#define OW 8                       // o-rows per block (one per warp)
#define BITERS 8                   // b iterations per block
#define OGROUPS (HH / OW)          // 128
#define BGROUPS (BB / BITERS)      // 8
#define STAGES 2

// SMEM layout (dynamic)
#define G_BYTES (OW * HH * 4)            // 32768: gumbel[b, og*8 .. og*8+7, :]
#define H_BYTES (HH * 4)                 // 4096:  h_prev[b, :]
#define STAGE_BYTES (G_BYTES + H_BYTES)  // 36864
#define MBAR_OFF (STAGES * STAGE_BYTES)  // 73728
#define SMEM_BYTES (MBAR_OFF + 2 * 8)    // + 2 full-barriers

static __device__ __forceinline__ uint32_t s2u(const void* p) {
    uint32_t a;
    asm("{ .reg .u64 t; cvta.to.shared.u64 t, %1; cvt.u32.u64 %0, t; }"
        : "=r"(a) : "l"(p));
    return a;
}

static __device__ __forceinline__ void mbar_init(uint32_t mbar, uint32_t cnt) {
    asm volatile("mbarrier.init.shared.b64 [%0], %1;" :: "r"(mbar), "r"(cnt) : "memory");
}

static __device__ __forceinline__ void mbar_expect_tx(uint32_t mbar, uint32_t bytes) {
    asm volatile("mbarrier.arrive.expect_tx.shared.b64 _, [%0], %1;"
                 :: "r"(mbar), "r"(bytes) : "memory");
}

static __device__ __forceinline__ void mbar_wait(uint32_t mbar, uint32_t parity) {
    uint32_t done;
    asm volatile(
        "{\n\t.reg .pred p;\n\t"
        "mbarrier.try_wait.parity.acquire.cta.shared::cta.b64 p, [%1], %2;\n\t"
        "selp.b32 %0, 1, 0, p;\n\t}"
        : "=r"(done) : "r"(mbar), "r"(parity) : "memory");
    if (!done) {
        asm volatile(
            "{\n\t.reg .pred P1;\n\t"
            "WL_%=:\n\t"
            "mbarrier.try_wait.parity.acquire.cta.shared::cta.b64 P1, [%0], %1, 0x989680;\n\t"
            "@P1 bra.uni WD_%=;\n\t"
            "bra.uni WL_%=;\n\t"
            "WD_%=:\n\t}"
            :: "r"(mbar), "r"(parity) : "memory");
    }
}

static __device__ __forceinline__ void bulk_copy(uint32_t dst_smem, const void* src,
                                                 uint32_t bytes, uint32_t mbar) {
    asm volatile(
        "cp.async.bulk.shared::cta.global.mbarrier::complete_tx::bytes [%0], [%1], %2, [%3];"
        :: "r"(dst_smem), "l"(src), "r"(bytes), "r"(mbar) : "memory");
}

static __device__ __forceinline__ float ex2(float x) {
    float y;
    asm("ex2.approx.ftz.f32 %0, %1;" : "=f"(y) : "f"(x));
    return y;
}

// Fused ReservoirRNNCell step, TMA-style smem pipeline:
//   block = 8 contiguous o-rows (8 warps) x 8 b-iterations.
//   Per b-iteration, ONE cp.async.bulk streams the 32KB gumbel chunk
//   gumbel[b, og*8:og*8+8, :] + the 4KB h_prev[b,:] row into a 2-stage smem
//   ring; warps compute from smem (LDS), fully decoupled from DRAM latency.
//   W_hh row pre-scaled by inv_tau*log2e lives in 32 regs per warp and is
//   reused across all 8 b's. Softmax without max-subtraction is safe (logits
//   bounded ~18.5; validated rel_err 3.4e-7 in R1/R2).
__global__ __launch_bounds__(256, 2) void reservoir_cell_kernel(
    const float* __restrict__ x_t,         // (B, I)
    const float* __restrict__ h_prev,      // (B, H)
    const float* __restrict__ W_ih,        // (H, I)
    const float* __restrict__ b_ih,        // (H,)
    const float* __restrict__ W_hh,        // (H, H)
    const float* __restrict__ temperature, // scalar
    const float* __restrict__ gumbel,      // (B, H, H)
    float* __restrict__ out)               // (B, H)
{
    extern __shared__ float smem[];
    const uint32_t smem_u = s2u(smem);
    const uint32_t mbar0 = smem_u + MBAR_OFF;

    const int og = blockIdx.x % OGROUPS;
    const int bg = blockIdx.x / OGROUPS;
    const int b0 = bg * BITERS;
    const int o0 = og * OW;

    const int tid  = threadIdx.x;
    const int w    = tid >> 5;
    const int lane = tid & 31;
    const int o    = o0 + w;

    // ---- init barriers + prologue fills (stages 0 and 1) ----
    if (tid == 0) {
        mbar_init(mbar0, 1);
        mbar_init(mbar0 + 8, 1);
    }
    __syncthreads();
    if (tid == 0) {
#pragma unroll
        for (int j = 0; j < STAGES; ++j) {
            const uint32_t mb = mbar0 + 8u * j;
            mbar_expect_tx(mb, STAGE_BYTES);
            const float* gsrc = gumbel + ((size_t)(b0 + j) * HH + o0) * HH;
            bulk_copy(smem_u + j * STAGE_BYTES, gsrc, G_BYTES, mb);
            const float* hsrc = h_prev + (size_t)(b0 + j) * HH;
            bulk_copy(smem_u + j * STAGE_BYTES + G_BYTES, hsrc, H_BYTES, mb);
        }
    }

    // ---- per-warp constants: pre-scaled W_hh row + W_ih row (registers) ----
    const float inv_tau_l2e = LOG2E / fmaxf(temperature[0], MIN_TAU);
    const float bias = b_ih[o];

    const float4* __restrict__ whr = reinterpret_cast<const float4*>(W_hh + (size_t)o * HH);
    float4 wp[8];
#pragma unroll
    for (int k = 0; k < 8; ++k) {
        float4 v = whr[lane + 32 * k];
        v.x *= inv_tau_l2e; v.y *= inv_tau_l2e;
        v.z *= inv_tau_l2e; v.w *= inv_tau_l2e;
        wp[k] = v;
    }
    const float4* __restrict__ wir = reinterpret_cast<const float4*>(W_ih + (size_t)o * II);
    float4 wih[4];
#pragma unroll
    for (int k = 0; k < 4; ++k) wih[k] = wir[lane + 32 * k];

    // ---- main loop over 8 b's with 2-stage pipeline ----
    for (int i = 0; i < BITERS; ++i) {
        const int st = i & 1;
        const uint32_t parity = (i >> 1) & 1;
        const int b = b0 + i;

        // input contribution (L1/L2-resident x_t) — overlaps the TMA wait
        const float4* __restrict__ xr = reinterpret_cast<const float4*>(x_t + (size_t)b * II);
        float ic = 0.0f;
#pragma unroll
        for (int k = 0; k < 4; ++k) {
            const float4 xv = xr[lane + 32 * k];
            ic = fmaf(xv.x, wih[k].x, ic);
            ic = fmaf(xv.y, wih[k].y, ic);
            ic = fmaf(xv.z, wih[k].z, ic);
            ic = fmaf(xv.w, wih[k].w, ic);
        }

        mbar_wait(mbar0 + 8u * st, parity);

        const float4* __restrict__ gs = reinterpret_cast<const float4*>(
            smem + (size_t)st * (STAGE_BYTES / 4) + (size_t)w * HH);
        const float4* __restrict__ hs = reinterpret_cast<const float4*>(
            smem + (size_t)st * (STAGE_BYTES / 4) + G_BYTES / 4);

        float s = 0.0f, t = 0.0f;
#pragma unroll
        for (int k = 0; k < 8; ++k) {
            const int idx = lane + 32 * k;
            const float4 g = gs[idx];
            const float4 h = hs[idx];
            float e;
            e = ex2(fmaf(g.x, LOG2E, wp[k].x)); s += e; t = fmaf(e, h.x, t);
            e = ex2(fmaf(g.y, LOG2E, wp[k].y)); s += e; t = fmaf(e, h.y, t);
            e = ex2(fmaf(g.z, LOG2E, wp[k].z)); s += e; t = fmaf(e, h.z, t);
            e = ex2(fmaf(g.w, LOG2E, wp[k].w)); s += e; t = fmaf(e, h.w, t);
        }

        // warp reductions + output
#pragma unroll
        for (int off = 16; off > 0; off >>= 1) {
            s  += __shfl_xor_sync(0xffffffffu, s,  off);
            t  += __shfl_xor_sync(0xffffffffu, t,  off);
            ic += __shfl_xor_sync(0xffffffffu, ic, off);
        }
        if (lane == 0) {
            out[(size_t)b * HH + o] = tanhf(ic + bias + t / s);
        }

        // all warps done reading this stage -> refill for iteration i+2
        __syncthreads();
        if (tid == 0 && i + STAGES < BITERS) {
            const int j = i + STAGES;
            const uint32_t mb = mbar0 + 8u * st;
            mbar_expect_tx(mb, STAGE_BYTES);
            const float* gsrc = gumbel + ((size_t)(b0 + j) * HH + o0) * HH;
            bulk_copy(smem_u + st * STAGE_BYTES, gsrc, G_BYTES, mb);
            const float* hsrc = h_prev + (size_t)(b0 + j) * HH;
            bulk_copy(smem_u + st * STAGE_BYTES + G_BYTES, hsrc, H_BYTES, mb);
        }
    }
}

extern "C" void kernel_launch(void* const* d_in, const int* in_sizes, int n_in,
                              void* d_out, int out_size) {
    // metadata order: x_t, h_prev, W_ih, b_ih, W_hh, temperature, gumbel_noise
    const float* x_t    = (const float*)d_in[0];
    const float* h_prev = (const float*)d_in[1];
    const float* W_ih   = (const float*)d_in[2];
    const float* b_ih   = (const float*)d_in[3];
    const float* W_hh   = (const float*)d_in[4];
    const float* temp   = (const float*)d_in[5];
    const float* gum    = (const float*)d_in[6];
    float* out = (float*)d_out;

    static bool attr_set = false;
    if (!attr_set) {
        cudaFuncSetAttribute(reservoir_cell_kernel,
                             cudaFuncAttributeMaxDynamicSharedMemorySize, SMEM_BYTES);
        attr_set = true;
    }

    dim3 grid(OGROUPS * BGROUPS);  // 128 * 8 = 1024 blocks
    dim3 block(OW * 32);           // 256 threads, 8 warps
    reservoir_cell_kernel<<<grid, block, SMEM_BYTES>>>(
        x_t, h_prev, W_ih, b_ih, W_hh, temp, gum, out);
}